// round 1
// baseline (speedup 1.0000x reference)
#include <cuda_runtime.h>
#include <math.h>

// Scratch (allocation-free): pooled strips and fused gate strips.
// Sizes: B*C*PS = 8*64*16 = 8192 floats each.
__device__ float g_hp[8192];
__device__ float g_vp[8192];
__device__ float g_fh[8192];
__device__ float g_fv[8192];

// ---------------------------------------------------------------------------
// Kernel 1: strip pooling. One block per (b,c) plane of 256x256 fp32.
// hp[p] = mean over rows [16p,16p+16) x all 256 cols   (4096 elems)
// vp[q] = mean over all 256 rows x cols [16q,16q+16)   (4096 elems)
// 256 threads: tid = ry*64 + cg; thread owns float4 column-group cg,
// rows h == ry (mod 4). Its 4 columns lie in a single w-bin (cg>>2).
// ---------------------------------------------------------------------------
__global__ void __launch_bounds__(256) sp_pool_kernel(const float* __restrict__ x) {
    const int bc = blockIdx.x;                       // 0 .. 511
    const float4* __restrict__ plane =
        reinterpret_cast<const float4*>(x + (size_t)bc * 65536);

    const int tid  = threadIdx.x;
    const int ry   = tid >> 6;      // 0..3
    const int cg   = tid & 63;      // float4 column group 0..63
    const int lane = tid & 31;

    __shared__ float s_h[16];
    __shared__ float s_w[16];
    if (tid < 16) { s_h[tid] = 0.f; s_w[tid] = 0.f; }
    __syncthreads();

    float wacc = 0.f;
    for (int p = 0; p < 16; ++p) {
        float hacc = 0.f;
#pragma unroll
        for (int j = 0; j < 4; ++j) {
            const int h = p * 16 + ry + 4 * j;
            float4 v = plane[h * 64 + cg];
            hacc += (v.x + v.y) + (v.z + v.w);
        }
        wacc += hacc;
        // warp reduce hacc (all lanes in a warp share the same p)
#pragma unroll
        for (int off = 16; off; off >>= 1)
            hacc += __shfl_down_sync(0xffffffffu, hacc, off);
        if (lane == 0) atomicAdd(&s_h[p], hacc);
    }
    // reduce wacc within groups of 4 lanes (same w-bin: cg>>2)
    wacc += __shfl_down_sync(0xffffffffu, wacc, 2);
    wacc += __shfl_down_sync(0xffffffffu, wacc, 1);
    if ((lane & 3) == 0) atomicAdd(&s_w[cg >> 2], wacc);

    __syncthreads();
    if (tid < 16) {
        g_hp[bc * 16 + tid] = s_h[tid] * (1.0f / 4096.0f);
        g_vp[bc * 16 + tid] = s_w[tid] * (1.0f / 4096.0f);
    }
}

// ---------------------------------------------------------------------------
// Kernel 2: tiny linear + BN chain on the 64x16 pooled strips. One block per
// batch element (8 blocks, 256 threads).
//   hpn = BN_h(Wh @ hp + bh);  vpn = BN_v(Wv @ vp + bv)
//   fh' = invf * (Wf[:, :C] @ hpn)
//   fv' = invf * (Wf[:, C:] @ vpn + bf) + (beta_f - mean_f*invf)
// so that fusion = fh'[h-bin] + fv'[w-bin] in the final pass.
// ---------------------------------------------------------------------------
__global__ void __launch_bounds__(256) sp_mix_kernel(
    const float* __restrict__ Wh, const float* __restrict__ bh,
    const float* __restrict__ Wv, const float* __restrict__ bv,
    const float* __restrict__ Wf, const float* __restrict__ bf,
    const float* __restrict__ hg, const float* __restrict__ hb,
    const float* __restrict__ hm, const float* __restrict__ hv,
    const float* __restrict__ vg, const float* __restrict__ vb,
    const float* __restrict__ vm, const float* __restrict__ vv,
    const float* __restrict__ fg, const float* __restrict__ fb,
    const float* __restrict__ fm, const float* __restrict__ fvr)
{
    __shared__ float s_hp[1024];   // [c][p], c=64, p=16
    __shared__ float s_vp[1024];
    __shared__ float s_hpn[1024];
    __shared__ float s_vpn[1024];

    const int b   = blockIdx.x;
    const int tid = threadIdx.x;

    for (int i = tid; i < 1024; i += 256) {
        s_hp[i] = g_hp[b * 1024 + i];
        s_vp[i] = g_vp[b * 1024 + i];
    }
    __syncthreads();

    for (int i = tid; i < 1024; i += 256) {
        const int o = i >> 4;
        const int p = i & 15;
        float ah = 0.f, av = 0.f;
#pragma unroll 8
        for (int c = 0; c < 64; ++c) {
            ah += Wh[o * 64 + c] * s_hp[c * 16 + p];
            av += Wv[o * 64 + c] * s_vp[c * 16 + p];
        }
        const float invh = hg[o] * rsqrtf(hv[o] + 1e-5f);
        const float invv = vg[o] * rsqrtf(vv[o] + 1e-5f);
        s_hpn[i] = (ah + bh[o]) * invh + (hb[o] - hm[o] * invh);
        s_vpn[i] = (av + bv[o]) * invv + (vb[o] - vm[o] * invv);
    }
    __syncthreads();

    for (int i = tid; i < 1024; i += 256) {
        const int o = i >> 4;
        const int p = i & 15;
        float ah = 0.f, av = 0.f;
#pragma unroll 8
        for (int c = 0; c < 64; ++c) {
            ah += Wf[o * 128 + c]      * s_hpn[c * 16 + p];
            av += Wf[o * 128 + 64 + c] * s_vpn[c * 16 + p];
        }
        const float invf = fg[o] * rsqrtf(fvr[o] + 1e-5f);
        g_fh[b * 1024 + i] = ah * invf;
        g_fv[b * 1024 + i] = (av + bf[o]) * invf + (fb[o] - fm[o] * invf);
    }
}

// ---------------------------------------------------------------------------
// Kernel 3: out = sigmoid(fh'[b,c,h>>4] + fv'[b,c,w>>4]) * x.
// Pure streaming float4 kernel. The sigmoid argument is constant across the
// 4 lanes of each aligned float4 (w-bin width 16 >= 4).
// ---------------------------------------------------------------------------
__global__ void __launch_bounds__(256) sp_gate_kernel(
    const float4* __restrict__ x4, float4* __restrict__ out4)
{
    const int i = blockIdx.x * 256 + threadIdx.x;   // 0 .. 8388607
    const int w4   = i & 63;          // float4 index along w
    const int rest = i >> 6;
    const int h    = rest & 255;
    const int bc   = rest >> 8;

    const float z = g_fh[bc * 16 + (h >> 4)] + g_fv[bc * 16 + (w4 >> 2)];
    const float s = 1.0f / (1.0f + expf(-z));

    float4 v = x4[i];
    v.x *= s; v.y *= s; v.z *= s; v.w *= s;
    out4[i] = v;
}

// ---------------------------------------------------------------------------
extern "C" void kernel_launch(void* const* d_in, const int* in_sizes, int n_in,
                              void* d_out, int out_size)
{
    const float* x  = (const float*)d_in[0];
    const float* Wh = (const float*)d_in[1];
    const float* bh = (const float*)d_in[2];
    const float* Wv = (const float*)d_in[3];
    const float* bv = (const float*)d_in[4];
    const float* Wf = (const float*)d_in[5];
    const float* bf = (const float*)d_in[6];
    const float* hg = (const float*)d_in[7];
    const float* hb = (const float*)d_in[8];
    const float* hm = (const float*)d_in[9];
    const float* hv = (const float*)d_in[10];
    const float* vg = (const float*)d_in[11];
    const float* vb = (const float*)d_in[12];
    const float* vm = (const float*)d_in[13];
    const float* vv = (const float*)d_in[14];
    const float* fg = (const float*)d_in[15];
    const float* fb = (const float*)d_in[16];
    const float* fm = (const float*)d_in[17];
    const float* fv = (const float*)d_in[18];

    // B*C = 512 planes
    sp_pool_kernel<<<512, 256>>>(x);
    sp_mix_kernel<<<8, 256>>>(Wh, bh, Wv, bv, Wf, bf,
                              hg, hb, hm, hv,
                              vg, vb, vm, vv,
                              fg, fb, fm, fv);
    // 8*64*256*256 / 4 = 8388608 float4 -> 32768 blocks of 256
    sp_gate_kernel<<<32768, 256>>>((const float4*)x, (float4*)d_out);
}

// round 2
// speedup vs baseline: 1.0867x; 1.0867x over previous
#include <cuda_runtime.h>
#include <math.h>

// Scratch (allocation-free): pooled strips and fused gate strips.
__device__ float g_hp[8192];
__device__ float g_vp[8192];
__device__ float g_fh[8192];
__device__ float g_fv[8192];

// ---------------------------------------------------------------------------
// Kernel 1: strip pooling. One block per (b,c) plane of 256x256 fp32.
// Register-accumulated: 16 per-p partials + 1 w accumulator; all 64 float4
// loads are independent -> high MLP. Reductions happen once at the end.
// tid = ry*64 + cg ; thread owns float4-column cg, rows ry*4..ry*4+3 of each
// 16-row h-bin. Its 4 columns lie in one w-bin (cg>>2).
// ---------------------------------------------------------------------------
__global__ void __launch_bounds__(256) sp_pool_kernel(const float* __restrict__ x) {
    const int bc = blockIdx.x;                       // 0 .. 511
    const float4* __restrict__ plane =
        reinterpret_cast<const float4*>(x + (size_t)bc * 65536);

    const int tid  = threadIdx.x;
    const int ry   = tid >> 6;      // 0..3
    const int cg   = tid & 63;      // float4 column group
    const int lane = tid & 31;

    __shared__ float s_h[16];
    __shared__ float s_w[16];
    if (tid < 16) { s_h[tid] = 0.f; s_w[tid] = 0.f; }
    __syncthreads();

    float accp[16];
#pragma unroll
    for (int p = 0; p < 16; ++p) accp[p] = 0.f;

#pragma unroll
    for (int p = 0; p < 16; ++p) {
#pragma unroll
        for (int j = 0; j < 4; ++j) {
            const int h = p * 16 + ry * 4 + j;
            float4 v = plane[h * 64 + cg];
            accp[p] += (v.x + v.y) + (v.z + v.w);
        }
    }

    float wacc = 0.f;
#pragma unroll
    for (int p = 0; p < 16; ++p) wacc += accp[p];

    // h-bin reductions: warp-reduce each accp[p], one atomic per warp per p.
#pragma unroll
    for (int p = 0; p < 16; ++p) {
        float v = accp[p];
#pragma unroll
        for (int off = 16; off; off >>= 1)
            v += __shfl_down_sync(0xffffffffu, v, off);
        if (lane == 0) atomicAdd(&s_h[p], v);
    }
    // w-bin: lanes are consecutive cg; groups of 4 lanes share w-bin cg>>2.
    wacc += __shfl_down_sync(0xffffffffu, wacc, 2);
    wacc += __shfl_down_sync(0xffffffffu, wacc, 1);
    if ((lane & 3) == 0) atomicAdd(&s_w[cg >> 2], wacc);

    __syncthreads();
    if (tid < 16) {
        g_hp[bc * 16 + tid] = s_h[tid] * (1.0f / 4096.0f);
        g_vp[bc * 16 + tid] = s_w[tid] * (1.0f / 4096.0f);
    }
}

// ---------------------------------------------------------------------------
// Kernel 2: tiny linear + BN chain (unchanged, ~2us, negligible).
// ---------------------------------------------------------------------------
__global__ void __launch_bounds__(256) sp_mix_kernel(
    const float* __restrict__ Wh, const float* __restrict__ bh,
    const float* __restrict__ Wv, const float* __restrict__ bv,
    const float* __restrict__ Wf, const float* __restrict__ bf,
    const float* __restrict__ hg, const float* __restrict__ hb,
    const float* __restrict__ hm, const float* __restrict__ hv,
    const float* __restrict__ vg, const float* __restrict__ vb,
    const float* __restrict__ vm, const float* __restrict__ vv,
    const float* __restrict__ fg, const float* __restrict__ fb,
    const float* __restrict__ fm, const float* __restrict__ fvr)
{
    __shared__ float s_hp[1024];   // [c][p]
    __shared__ float s_vp[1024];
    __shared__ float s_hpn[1024];
    __shared__ float s_vpn[1024];

    const int b   = blockIdx.x;
    const int tid = threadIdx.x;

    for (int i = tid; i < 1024; i += 256) {
        s_hp[i] = g_hp[b * 1024 + i];
        s_vp[i] = g_vp[b * 1024 + i];
    }
    __syncthreads();

    for (int i = tid; i < 1024; i += 256) {
        const int o = i >> 4;
        const int p = i & 15;
        float ah = 0.f, av = 0.f;
#pragma unroll 8
        for (int c = 0; c < 64; ++c) {
            ah += Wh[o * 64 + c] * s_hp[c * 16 + p];
            av += Wv[o * 64 + c] * s_vp[c * 16 + p];
        }
        const float invh = hg[o] * rsqrtf(hv[o] + 1e-5f);
        const float invv = vg[o] * rsqrtf(vv[o] + 1e-5f);
        s_hpn[i] = (ah + bh[o]) * invh + (hb[o] - hm[o] * invh);
        s_vpn[i] = (av + bv[o]) * invv + (vb[o] - vm[o] * invv);
    }
    __syncthreads();

    for (int i = tid; i < 1024; i += 256) {
        const int o = i >> 4;
        const int p = i & 15;
        float ah = 0.f, av = 0.f;
#pragma unroll 8
        for (int c = 0; c < 64; ++c) {
            ah += Wf[o * 128 + c]      * s_hpn[c * 16 + p];
            av += Wf[o * 128 + 64 + c] * s_vpn[c * 16 + p];
        }
        const float invf = fg[o] * rsqrtf(fvr[o] + 1e-5f);
        g_fh[b * 1024 + i] = ah * invf;
        g_fv[b * 1024 + i] = (av + bf[o]) * invf + (fb[o] - fm[o] * invf);
    }
}

// ---------------------------------------------------------------------------
// Kernel 3: out = sigmoid(fh'[b,c,h>>4] + fv'[b,c,w>>4]) * x.
// One block = 8 contiguous rows of one plane => exactly one h-bin.
// 16 sigmoids precomputed in shared once; each thread streams 2 float4 with
// evict-first loads/stores (.cs) so gate traffic does not displace the x
// lines that the pool kernel left in L2 (L2 ~126MB vs x=134MB => most of x
// is still resident). Rows processed bottom-up to read the cached plane
// tails first.
// ---------------------------------------------------------------------------
__global__ void __launch_bounds__(256) sp_gate_kernel(
    const float4* __restrict__ x4, float4* __restrict__ out4)
{
    const int blk   = blockIdx.x;          // 0..16383
    const int plane = blk >> 5;            // bc
    const int rb    = 31 - (blk & 31);     // row-block, reversed within plane

    __shared__ float s_sig[16];
    if (threadIdx.x < 16) {
        const float z = g_fh[plane * 16 + (rb >> 1)] + g_fv[plane * 16 + threadIdx.x];
        s_sig[threadIdx.x] = 1.0f / (1.0f + expf(-z));
    }
    __syncthreads();

    const size_t base = (size_t)plane * 16384 + (size_t)rb * 512;  // float4 units

#pragma unroll
    for (int j = 0; j < 2; ++j) {
        const int idx = j * 256 + threadIdx.x;
        float4 v = __ldcs(&x4[base + idx]);
        const float s = s_sig[(idx & 63) >> 2];
        v.x *= s; v.y *= s; v.z *= s; v.w *= s;
        __stcs(&out4[base + idx], v);
    }
}

// ---------------------------------------------------------------------------
extern "C" void kernel_launch(void* const* d_in, const int* in_sizes, int n_in,
                              void* d_out, int out_size)
{
    const float* x  = (const float*)d_in[0];
    const float* Wh = (const float*)d_in[1];
    const float* bh = (const float*)d_in[2];
    const float* Wv = (const float*)d_in[3];
    const float* bv = (const float*)d_in[4];
    const float* Wf = (const float*)d_in[5];
    const float* bf = (const float*)d_in[6];
    const float* hg = (const float*)d_in[7];
    const float* hb = (const float*)d_in[8];
    const float* hm = (const float*)d_in[9];
    const float* hv = (const float*)d_in[10];
    const float* vg = (const float*)d_in[11];
    const float* vb = (const float*)d_in[12];
    const float* vm = (const float*)d_in[13];
    const float* vv = (const float*)d_in[14];
    const float* fg = (const float*)d_in[15];
    const float* fb = (const float*)d_in[16];
    const float* fm = (const float*)d_in[17];
    const float* fv = (const float*)d_in[18];

    sp_pool_kernel<<<512, 256>>>(x);
    sp_mix_kernel<<<8, 256>>>(Wh, bh, Wv, bv, Wf, bf,
                              hg, hb, hm, hv,
                              vg, vb, vm, vv,
                              fg, fb, fm, fv);
    sp_gate_kernel<<<16384, 256>>>((const float4*)x, (float4*)d_out);
}

// round 3
// speedup vs baseline: 1.1110x; 1.0223x over previous
#include <cuda_runtime.h>
#include <math.h>

// Scratch (allocation-free).
__device__ float g_hp[8192];          // [bc][p]    raw means
__device__ float g_vp_part[16384];    // [half][bc][q]  raw sums (pre-mean)
__device__ float g_fh[8192];          // [bc][p]
__device__ float g_fv[8192];          // [bc][q]
__device__ float g_sig[131072];       // [bc][p][q] precomputed sigmoids

// ---------------------------------------------------------------------------
// Kernel 1: strip pooling. One block per 128-row half-plane (grid 1024).
// Covers h-bins [half*8, half*8+8) fully; w-bins partially (summed in mix).
// tid = ry*64 + cg; thread owns float4-column cg, rows ry*4..ry*4+3 of each
// 16-row h-bin. Its 4 columns lie in one w-bin (cg>>2).
// ---------------------------------------------------------------------------
__global__ void __launch_bounds__(256) sp_pool_kernel(const float* __restrict__ x) {
    const int blk  = blockIdx.x;          // 0..1023
    const int bc   = blk >> 1;
    const int half = blk & 1;
    const float4* __restrict__ plane =
        reinterpret_cast<const float4*>(x + (size_t)bc * 65536) + half * 8192;

    const int tid  = threadIdx.x;
    const int ry   = tid >> 6;
    const int cg   = tid & 63;
    const int lane = tid & 31;

    __shared__ float s_h[8];
    __shared__ float s_w[16];
    if (tid < 8)  s_h[tid] = 0.f;
    if (tid < 16) s_w[tid] = 0.f;
    __syncthreads();

    float accp[8];
#pragma unroll
    for (int p = 0; p < 8; ++p) accp[p] = 0.f;

#pragma unroll
    for (int p = 0; p < 8; ++p) {
#pragma unroll
        for (int j = 0; j < 4; ++j) {
            const int h = p * 16 + ry * 4 + j;     // row within half-plane
            float4 v = plane[h * 64 + cg];
            accp[p] += (v.x + v.y) + (v.z + v.w);
        }
    }

    float wacc = 0.f;
#pragma unroll
    for (int p = 0; p < 8; ++p) wacc += accp[p];

#pragma unroll
    for (int p = 0; p < 8; ++p) {
        float v = accp[p];
#pragma unroll
        for (int off = 16; off; off >>= 1)
            v += __shfl_down_sync(0xffffffffu, v, off);
        if (lane == 0) atomicAdd(&s_h[p], v);
    }
    wacc += __shfl_down_sync(0xffffffffu, wacc, 2);
    wacc += __shfl_down_sync(0xffffffffu, wacc, 1);
    if ((lane & 3) == 0) atomicAdd(&s_w[cg >> 2], wacc);

    __syncthreads();
    if (tid < 8)
        g_hp[bc * 16 + half * 8 + tid] = s_h[tid] * (1.0f / 4096.0f);
    if (tid < 16)
        g_vp_part[half * 8192 + bc * 16 + tid] = s_w[tid];
}

// ---------------------------------------------------------------------------
// Kernel 2: tiny linear + BN chain. One block per batch (8 blocks).
// ---------------------------------------------------------------------------
__global__ void __launch_bounds__(256) sp_mix_kernel(
    const float* __restrict__ Wh, const float* __restrict__ bh,
    const float* __restrict__ Wv, const float* __restrict__ bv,
    const float* __restrict__ Wf, const float* __restrict__ bf,
    const float* __restrict__ hg, const float* __restrict__ hb,
    const float* __restrict__ hm, const float* __restrict__ hv,
    const float* __restrict__ vg, const float* __restrict__ vb,
    const float* __restrict__ vm, const float* __restrict__ vv,
    const float* __restrict__ fg, const float* __restrict__ fb,
    const float* __restrict__ fm, const float* __restrict__ fvr)
{
    __shared__ float s_hp[1024];   // [c][p]
    __shared__ float s_vp[1024];
    __shared__ float s_hpn[1024];
    __shared__ float s_vpn[1024];

    const int b   = blockIdx.x;
    const int tid = threadIdx.x;

    for (int i = tid; i < 1024; i += 256) {
        s_hp[i] = g_hp[b * 1024 + i];
        s_vp[i] = (g_vp_part[b * 1024 + i] + g_vp_part[8192 + b * 1024 + i])
                  * (1.0f / 4096.0f);
    }
    __syncthreads();

    for (int i = tid; i < 1024; i += 256) {
        const int o = i >> 4;
        const int p = i & 15;
        float ah = 0.f, av = 0.f;
#pragma unroll 8
        for (int c = 0; c < 64; ++c) {
            ah += Wh[o * 64 + c] * s_hp[c * 16 + p];
            av += Wv[o * 64 + c] * s_vp[c * 16 + p];
        }
        const float invh = hg[o] * rsqrtf(hv[o] + 1e-5f);
        const float invv = vg[o] * rsqrtf(vv[o] + 1e-5f);
        s_hpn[i] = (ah + bh[o]) * invh + (hb[o] - hm[o] * invh);
        s_vpn[i] = (av + bv[o]) * invv + (vb[o] - vm[o] * invv);
    }
    __syncthreads();

    for (int i = tid; i < 1024; i += 256) {
        const int o = i >> 4;
        const int p = i & 15;
        float ah = 0.f, av = 0.f;
#pragma unroll 8
        for (int c = 0; c < 64; ++c) {
            ah += Wf[o * 128 + c]      * s_hpn[c * 16 + p];
            av += Wf[o * 128 + 64 + c] * s_vpn[c * 16 + p];
        }
        const float invf = fg[o] * rsqrtf(fvr[o] + 1e-5f);
        g_fh[b * 1024 + i] = ah * invf;
        g_fv[b * 1024 + i] = (av + bf[o]) * invf + (fb[o] - fm[o] * invf);
    }
}

// ---------------------------------------------------------------------------
// Kernel 2b: precompute all sigmoid gates. One block per plane (512 blocks),
// thread i computes (p,q) = (i>>4, i&15).
// ---------------------------------------------------------------------------
__global__ void __launch_bounds__(256) sp_sig_kernel() {
    const int bc = blockIdx.x;
    const int i  = threadIdx.x;
    const float z = g_fh[bc * 16 + (i >> 4)] + g_fv[bc * 16 + (i & 15)];
    g_sig[bc * 256 + i] = 1.0f / (1.0f + expf(-z));
}

// ---------------------------------------------------------------------------
// Kernel 3: out = sig[bc, h>>4, w>>4] * x. One block per 32-row chunk
// (grid 4096, 32KB r + 32KB w per block). Reverse scheduling order so the
// x lines the pool kernel read LAST (still L2-resident) are consumed first;
// .cs on loads and stores keeps gate traffic from displacing the rest.
// Thread t has a fixed w-bin ((t&63)>>2); its 8 float4 span the chunk's
// 2 h-bins (j<4 -> first, j>=4 -> second).
// ---------------------------------------------------------------------------
__global__ void __launch_bounds__(256) sp_gate_kernel(
    const float4* __restrict__ x4, float4* __restrict__ out4)
{
    const int rblk  = 4095 - blockIdx.x;
    const int plane = rblk >> 3;
    const int chunk = rblk & 7;
    const size_t base = (size_t)plane * 16384 + (size_t)chunk * 2048;

    const int t  = threadIdx.x;
    const int wb = (t & 63) >> 2;

    const float* __restrict__ sig = g_sig + plane * 256 + chunk * 32;
    const float s0 = __ldg(&sig[wb]);
    const float s1 = __ldg(&sig[16 + wb]);

#pragma unroll
    for (int j = 0; j < 8; ++j) {
        const float s = (j < 4) ? s0 : s1;
        const size_t idx = base + j * 256 + t;
        float4 v = __ldcs(&x4[idx]);
        v.x *= s; v.y *= s; v.z *= s; v.w *= s;
        __stcs(&out4[idx], v);
    }
}

// ---------------------------------------------------------------------------
extern "C" void kernel_launch(void* const* d_in, const int* in_sizes, int n_in,
                              void* d_out, int out_size)
{
    const float* x  = (const float*)d_in[0];
    const float* Wh = (const float*)d_in[1];
    const float* bh = (const float*)d_in[2];
    const float* Wv = (const float*)d_in[3];
    const float* bv = (const float*)d_in[4];
    const float* Wf = (const float*)d_in[5];
    const float* bf = (const float*)d_in[6];
    const float* hg = (const float*)d_in[7];
    const float* hb = (const float*)d_in[8];
    const float* hm = (const float*)d_in[9];
    const float* hv = (const float*)d_in[10];
    const float* vg = (const float*)d_in[11];
    const float* vb = (const float*)d_in[12];
    const float* vm = (const float*)d_in[13];
    const float* vv = (const float*)d_in[14];
    const float* fg = (const float*)d_in[15];
    const float* fb = (const float*)d_in[16];
    const float* fm = (const float*)d_in[17];
    const float* fv = (const float*)d_in[18];

    sp_pool_kernel<<<1024, 256>>>(x);
    sp_mix_kernel<<<8, 256>>>(Wh, bh, Wv, bv, Wf, bf,
                              hg, hb, hm, hv,
                              vg, vb, vm, vv,
                              fg, fb, fm, fv);
    sp_sig_kernel<<<512, 256>>>();
    sp_gate_kernel<<<4096, 256>>>((const float4*)x, (float4*)d_out);
}